// round 12
// baseline (speedup 1.0000x reference)
#include <cuda_runtime.h>
#include <cuda_bf16.h>

// SE3Transform (PARTIAL_DENSE): for m in [0,M), i in [0,N):
//   nb = batch[i] + m*B;  out_pos[m*N+i] = R[nb] @ xyz[i] + p[nb];  out_batch[m*N+i] = nb
// Inputs: trans [M*B,4,4] f32, xyz [N,3] f32, batch [N] i32.
// Output: new_pos.ravel() [M*N*3] f32 ++ new_batch [M*N] as f32.
//
// R11 findings: 8 configs all ~21-23us; no pipe >55%; scheduling axes all
// neutral. Hypothesis: warps are phase-locked (identical code after one
// syncthreads) -> bursty LSU demand (all-LDS / all-FMA / all-STG phases),
// time-avg port util ~55%.
// R12: stagger slice order per warp: m = (s + warpId) & 7. Zero extra work;
// flattens port demand. Everything else frozen from the 21.3us best.

#define BATCH_B 16
#define NMAT    128          // M*B
#define NPAIR   6            // float2 pairs per matrix (12 floats)
#define NSM     152          // GB300 SM count

__device__ __forceinline__ void slice_body(
        const float2* __restrict__ s2, float* __restrict__ out,
        const float x[4], const float y[4], const float z[4],
        const int b0[4], const float fb0[4],
        int m, int i0, int N, long long posElems, int writeBatch)
{
    const int mB = m * BATCH_B;
    const float fmB = (float)mB;
    const long long sliceBase = (long long)m * N;

    float o[12];
    #pragma unroll
    for (int k = 0; k < 4; k++) {
        int nb = b0[k] + mB;
        float2 p0 = s2[0 * NMAT + nb];  // r00 r01
        float2 p1 = s2[1 * NMAT + nb];  // r02 tx
        float2 p2 = s2[2 * NMAT + nb];  // r10 r11
        float2 p3 = s2[3 * NMAT + nb];  // r12 ty
        float2 p4 = s2[4 * NMAT + nb];  // r20 r21
        float2 p5 = s2[5 * NMAT + nb];  // r22 tz
        o[k*3+0] = fmaf(p0.x, x[k], fmaf(p0.y, y[k], fmaf(p1.x, z[k], p1.y)));
        o[k*3+1] = fmaf(p2.x, x[k], fmaf(p2.y, y[k], fmaf(p3.x, z[k], p3.y)));
        o[k*3+2] = fmaf(p4.x, x[k], fmaf(p4.y, y[k], fmaf(p5.x, z[k], p5.y)));
    }

    float4* outv = (float4*)(out + (sliceBase + i0) * 3);
    outv[0] = make_float4(o[0], o[1], o[2],  o[3]);
    outv[1] = make_float4(o[4], o[5], o[6],  o[7]);
    outv[2] = make_float4(o[8], o[9], o[10], o[11]);

    if (writeBatch) {
        float4* bo = (float4*)(out + posElems + sliceBase + i0);
        *bo = make_float4(fb0[0] + fmB, fb0[1] + fmB,
                          fb0[2] + fmB, fb0[3] + fmB);
    }
}

__global__ void __launch_bounds__(832, 1) se3_kernel(
        const float*  __restrict__ trans,
        const float4* __restrict__ xyz4,
        const float*  __restrict__ xyz,
        const int4*   __restrict__ batch4,
        const int*    __restrict__ batch,
        float* __restrict__ out,
        int N, int G, int M,
        long long posElems, int writeBatch)
{
    // float2-SoA transform table: s2[j*NMAT + mat] = (trans[mat][2j], trans[mat][2j+1])
    __shared__ float2 s2[NPAIR * NMAT];   // 6 KB, conflict-free gathers

    for (int idx = threadIdx.x; idx < NPAIR * NMAT; idx += blockDim.x) {
        int j   = idx >> 7;
        int mat = idx & 127;
        const float2* src = (const float2*)(trans + mat * 16);
        s2[idx] = __ldg(&src[j]);
    }
    __syncthreads();

    // Balanced contiguous group range for this CTA (one CTA per SM).
    const int gStart = (int)((long long)blockIdx.x * G / gridDim.x);
    const int gEnd   = (int)((long long)(blockIdx.x + 1) * G / gridDim.x);
    const int g = gStart + threadIdx.x;
    if (g >= gEnd) return;

    const int i0 = g * 4;
    const int wid = threadIdx.x >> 5;     // warp id for phase staggering

    if (i0 + 3 < N) {
        // ---- load 4 points once (the only input reads) ----
        float4 a = __ldg(&xyz4[g * 3 + 0]);
        float4 b = __ldg(&xyz4[g * 3 + 1]);
        float4 c = __ldg(&xyz4[g * 3 + 2]);
        int4  bt = __ldg(&batch4[g]);

        float x[4], y[4], z[4];
        x[0] = a.x; y[0] = a.y; z[0] = a.z;
        x[1] = a.w; y[1] = b.x; z[1] = b.y;
        x[2] = b.z; y[2] = b.w; z[2] = c.x;
        x[3] = c.y; y[3] = c.z; z[3] = c.w;

        int b0[4];
        b0[0] = bt.x; b0[1] = bt.y; b0[2] = bt.z; b0[3] = bt.w;
        float fb0[4];
        fb0[0] = (float)bt.x; fb0[1] = (float)bt.y;
        fb0[2] = (float)bt.z; fb0[3] = (float)bt.w;

        if (M == 8) {
            // Staggered slice order: warp w starts at slice (w&7) -> warps sit
            // in different LDS/FMA/STG phases at any instant, flattening the
            // LSU demand instead of hitting it in lockstep bursts.
            const int mStart = wid & 7;
            #pragma unroll
            for (int s = 0; s < 8; s++) {
                int m = (mStart + s) & 7;
                slice_body(s2, out, x, y, z, b0, fb0,
                           m, i0, N, posElems, writeBatch);
            }
        } else {
            for (int s = 0; s < M; s++) {
                int m = (wid + s) % M;
                slice_body(s2, out, x, y, z, b0, fb0,
                           m, i0, N, posElems, writeBatch);
            }
        }
    } else {
        // ---- scalar tail (unused when N % 4 == 0, kept for safety) ----
        for (int i = i0; i < N; i++) {
            float px = xyz[i * 3 + 0];
            float py = xyz[i * 3 + 1];
            float pz = xyz[i * 3 + 2];
            int bi = __ldg(&batch[i]);
            for (int m = 0; m < M; m++) {
                int nb = bi + m * BATCH_B;
                float2 p0 = s2[0 * NMAT + nb];
                float2 p1 = s2[1 * NMAT + nb];
                float2 p2 = s2[2 * NMAT + nb];
                float2 p3 = s2[3 * NMAT + nb];
                float2 p4 = s2[4 * NMAT + nb];
                float2 p5 = s2[5 * NMAT + nb];
                long long ob = ((long long)m * N + i) * 3;
                out[ob + 0] = fmaf(p0.x, px, fmaf(p0.y, py, fmaf(p1.x, pz, p1.y)));
                out[ob + 1] = fmaf(p2.x, px, fmaf(p2.y, py, fmaf(p3.x, pz, p3.y)));
                out[ob + 2] = fmaf(p4.x, px, fmaf(p4.y, py, fmaf(p5.x, pz, p5.y)));
                if (writeBatch)
                    out[posElems + (long long)m * N + i] = (float)nb;
            }
        }
    }
}

extern "C" void kernel_launch(void* const* d_in, const int* in_sizes, int n_in,
                              void* d_out, int out_size) {
    const float* trans = (const float*)d_in[0];   // [M*B, 4, 4]
    const float* xyz   = (const float*)d_in[1];   // [N, 3]
    const int*   batch = (const int*)d_in[2];     // [N]

    int numMat = in_sizes[0] / 16;        // M*B (= 128)
    int M      = numMat / BATCH_B;        // 8
    int N      = in_sizes[2];             // 500000

    long long posElems = (long long)M * N * 3;
    int writeBatch = ((long long)out_size >= posElems + (long long)M * N) ? 1 : 0;

    int G = (N + 3) / 4;                  // 4-point groups (125000)

    // One fat CTA per SM (mode-W): grid = 152 (GB300), 832 threads = 26 warps.
    int blocks = NSM;
    int threads = 832;
    int perCTA = (G + blocks - 1) / blocks;
    if (perCTA > threads) {
        blocks = (G + threads - 1) / threads;
    }

    se3_kernel<<<blocks, threads>>>(
        trans,
        (const float4*)xyz, xyz,
        (const int4*)batch, batch,
        (float*)d_out,
        N, G, M, posElems, writeBatch);
}

// round 13
// speedup vs baseline: 1.2460x; 1.2460x over previous
#include <cuda_runtime.h>
#include <cuda_bf16.h>

// SE3Transform (PARTIAL_DENSE): for m in [0,M), i in [0,N):
//   nb = batch[i] + m*B;  out_pos[m*N+i] = R[nb] @ xyz[i] + p[nb];  out_batch[m*N+i] = nb
// Inputs: trans [M*B,4,4] f32, xyz [N,3] f32, batch [N] i32.
// Output: new_pos.ravel() [M*N*3] f32 ++ new_batch [M*N] as f32.
//
// R12 findings: 9 configs ~21-23us; all scheduling axes neutral; store pattern
// (48B-stride STG.128 = 3x line inflation + HALF-SECTOR L2 writes -> RMW /
// queue backpressure) never tested.
// R13: warp-local smem staging per slice -> fully contiguous 512B STG.128
// (full lines, full sectors). Table + mode-W launch frozen from 21.3us best.

#define BATCH_B 16
#define NMAT    128          // M*B
#define NPAIR   6            // float2 pairs per matrix (12 floats)
#define NSM     152          // GB300 SM count
#define THREADS 832
#define WARPS   (THREADS / 32)   // 26

__global__ void __launch_bounds__(THREADS, 1) se3_kernel(
        const float*  __restrict__ trans,
        const float4* __restrict__ xyz4,
        const float*  __restrict__ xyz,
        const int4*   __restrict__ batch4,
        const int*    __restrict__ batch,
        float* __restrict__ out,
        int N, int G, int M,
        long long posElems, int writeBatch)
{
    // float2-SoA transform table (conflict-free gathers).
    __shared__ float2 s2[NPAIR * NMAT];          // 6 KB
    // Per-warp staging tile: 96 float4 = 1536 B per warp.
    __shared__ float4 sStage[WARPS * 96];        // 39.9 KB

    for (int idx = threadIdx.x; idx < NPAIR * NMAT; idx += blockDim.x) {
        int j   = idx >> 7;
        int mat = idx & 127;
        const float2* src = (const float2*)(trans + mat * 16);
        s2[idx] = __ldg(&src[j]);
    }
    __syncthreads();

    // Balanced contiguous group range for this CTA (one CTA per SM).
    const int gStart = (int)((long long)blockIdx.x * G / gridDim.x);
    const int gEnd   = (int)((long long)(blockIdx.x + 1) * G / gridDim.x);
    const int lane   = threadIdx.x & 31;
    const int wid    = threadIdx.x >> 5;
    const int g      = gStart + threadIdx.x;

    const int g0 = gStart + wid * 32;            // warp's first group
    const bool fullWarp = (g0 + 32 <= gEnd) && ((long long)(g0 + 32) * 4 <= N);

    if (fullWarp) {
        // ---- fast path: full warp, staged coalesced stores ----
        const int i0 = g * 4;
        float4 a = __ldg(&xyz4[g * 3 + 0]);
        float4 b = __ldg(&xyz4[g * 3 + 1]);
        float4 c = __ldg(&xyz4[g * 3 + 2]);
        int4  bt = __ldg(&batch4[g]);

        float x[4], y[4], z[4];
        x[0] = a.x; y[0] = a.y; z[0] = a.z;
        x[1] = a.w; y[1] = b.x; z[1] = b.y;
        x[2] = b.z; y[2] = b.w; z[2] = c.x;
        x[3] = c.y; y[3] = c.z; z[3] = c.w;

        int b0[4];
        b0[0] = bt.x; b0[1] = bt.y; b0[2] = bt.z; b0[3] = bt.w;
        float fb0[4];
        fb0[0] = (float)bt.x; fb0[1] = (float)bt.y;
        fb0[2] = (float)bt.z; fb0[3] = (float)bt.w;

        float4* stage = &sStage[wid * 96];

        #pragma unroll
        for (int m = 0; m < 8; m++) {
            const int mB = m * BATCH_B;
            const float fmB = (float)mB;
            const long long sliceBase = (long long)m * N;

            float o[12];
            #pragma unroll
            for (int k = 0; k < 4; k++) {
                int nb = b0[k] + mB;
                float2 p0 = s2[0 * NMAT + nb];
                float2 p1 = s2[1 * NMAT + nb];
                float2 p2 = s2[2 * NMAT + nb];
                float2 p3 = s2[3 * NMAT + nb];
                float2 p4 = s2[4 * NMAT + nb];
                float2 p5 = s2[5 * NMAT + nb];
                o[k*3+0] = fmaf(p0.x, x[k], fmaf(p0.y, y[k], fmaf(p1.x, z[k], p1.y)));
                o[k*3+1] = fmaf(p2.x, x[k], fmaf(p2.y, y[k], fmaf(p3.x, z[k], p3.y)));
                o[k*3+2] = fmaf(p4.x, x[k], fmaf(p4.y, y[k], fmaf(p5.x, z[k], p5.y)));
            }

            // Stage: lane l writes chunks 3l..3l+2 (48B) — conflict-free STS.128.
            float4* st = stage + lane * 3;
            st[0] = make_float4(o[0], o[1], o[2],  o[3]);
            st[1] = make_float4(o[4], o[5], o[6],  o[7]);
            st[2] = make_float4(o[8], o[9], o[10], o[11]);
            __syncwarp();

            // Drain: 3 fully contiguous 512B STG.128 (full lines, full sectors).
            float4* gbase = (float4*)(out + (sliceBase + (long long)g0 * 4) * 3);
            #pragma unroll
            for (int j = 0; j < 3; j++) {
                gbase[j * 32 + lane] = stage[j * 32 + lane];
            }
            __syncwarp();   // protect stage reuse next slice

            if (writeBatch) {   // already lane-contiguous (16B stride)
                float4* bo = (float4*)(out + posElems + sliceBase + i0);
                *bo = make_float4(fb0[0] + fmB, fb0[1] + fmB,
                                  fb0[2] + fmB, fb0[3] + fmB);
            }
        }
        return;
    }

    // ---- fallback: partial warp / tail (rare) ----
    if (g >= gEnd) return;
    const int i0 = g * 4;

    if (i0 + 3 < N) {
        float4 a = __ldg(&xyz4[g * 3 + 0]);
        float4 b = __ldg(&xyz4[g * 3 + 1]);
        float4 c = __ldg(&xyz4[g * 3 + 2]);
        int4  bt = __ldg(&batch4[g]);

        float x[4], y[4], z[4];
        x[0] = a.x; y[0] = a.y; z[0] = a.z;
        x[1] = a.w; y[1] = b.x; z[1] = b.y;
        x[2] = b.z; y[2] = b.w; z[2] = c.x;
        x[3] = c.y; y[3] = c.z; z[3] = c.w;

        int b0[4];
        b0[0] = bt.x; b0[1] = bt.y; b0[2] = bt.z; b0[3] = bt.w;
        float fb0[4];
        fb0[0] = (float)bt.x; fb0[1] = (float)bt.y;
        fb0[2] = (float)bt.z; fb0[3] = (float)bt.w;

        for (int m = 0; m < M; m++) {
            int mB = m * BATCH_B;
            float fmB = (float)mB;
            long long sliceBase = (long long)m * N;

            float o[12];
            #pragma unroll
            for (int k = 0; k < 4; k++) {
                int nb = b0[k] + mB;
                float2 p0 = s2[0 * NMAT + nb];
                float2 p1 = s2[1 * NMAT + nb];
                float2 p2 = s2[2 * NMAT + nb];
                float2 p3 = s2[3 * NMAT + nb];
                float2 p4 = s2[4 * NMAT + nb];
                float2 p5 = s2[5 * NMAT + nb];
                o[k*3+0] = fmaf(p0.x, x[k], fmaf(p0.y, y[k], fmaf(p1.x, z[k], p1.y)));
                o[k*3+1] = fmaf(p2.x, x[k], fmaf(p2.y, y[k], fmaf(p3.x, z[k], p3.y)));
                o[k*3+2] = fmaf(p4.x, x[k], fmaf(p4.y, y[k], fmaf(p5.x, z[k], p5.y)));
            }

            float4* outv = (float4*)(out + (sliceBase + i0) * 3);
            outv[0] = make_float4(o[0], o[1], o[2],  o[3]);
            outv[1] = make_float4(o[4], o[5], o[6],  o[7]);
            outv[2] = make_float4(o[8], o[9], o[10], o[11]);

            if (writeBatch) {
                float4* bo = (float4*)(out + posElems + sliceBase + i0);
                *bo = make_float4(fb0[0] + fmB, fb0[1] + fmB,
                                  fb0[2] + fmB, fb0[3] + fmB);
            }
        }
    } else {
        for (int i = i0; i < N; i++) {
            float px = xyz[i * 3 + 0];
            float py = xyz[i * 3 + 1];
            float pz = xyz[i * 3 + 2];
            int bi = __ldg(&batch[i]);
            for (int m = 0; m < M; m++) {
                int nb = bi + m * BATCH_B;
                float2 p0 = s2[0 * NMAT + nb];
                float2 p1 = s2[1 * NMAT + nb];
                float2 p2 = s2[2 * NMAT + nb];
                float2 p3 = s2[3 * NMAT + nb];
                float2 p4 = s2[4 * NMAT + nb];
                float2 p5 = s2[5 * NMAT + nb];
                long long ob = ((long long)m * N + i) * 3;
                out[ob + 0] = fmaf(p0.x, px, fmaf(p0.y, py, fmaf(p1.x, pz, p1.y)));
                out[ob + 1] = fmaf(p2.x, px, fmaf(p2.y, py, fmaf(p3.x, pz, p3.y)));
                out[ob + 2] = fmaf(p4.x, px, fmaf(p4.y, py, fmaf(p5.x, pz, p5.y)));
                if (writeBatch)
                    out[posElems + (long long)m * N + i] = (float)nb;
            }
        }
    }
}

extern "C" void kernel_launch(void* const* d_in, const int* in_sizes, int n_in,
                              void* d_out, int out_size) {
    const float* trans = (const float*)d_in[0];   // [M*B, 4, 4]
    const float* xyz   = (const float*)d_in[1];   // [N, 3]
    const int*   batch = (const int*)d_in[2];     // [N]

    int numMat = in_sizes[0] / 16;        // M*B (= 128)
    int M      = numMat / BATCH_B;        // 8
    int N      = in_sizes[2];             // 500000

    long long posElems = (long long)M * N * 3;
    int writeBatch = ((long long)out_size >= posElems + (long long)M * N) ? 1 : 0;

    int G = (N + 3) / 4;                  // 4-point groups (125000)

    // One fat CTA per SM (mode-W): grid = 152 (GB300), 832 threads = 26 warps.
    int blocks = NSM;
    int threads = THREADS;
    int perCTA = (G + blocks - 1) / blocks;
    if (perCTA > threads) {
        blocks = (G + threads - 1) / threads;
    }

    se3_kernel<<<blocks, threads>>>(
        trans,
        (const float4*)xyz, xyz,
        (const int4*)batch, batch,
        (float*)d_out,
        N, G, M, posElems, writeBatch);
}